// round 9
// baseline (speedup 1.0000x reference)
#include <cuda_runtime.h>
#include <cstdint>

#define N_NODES 100000
#define N_EDGES 300000
#define HID 256
#define SCAN_B 1024
#define N_BLK ((N_NODES + SCAN_B - 1) / SCAN_B)   // 98

// ---------------- scratch ----------------
__device__ float g_H[(size_t)N_NODES * HID];
__device__ float g_AGG[(size_t)N_NODES * HID];
__device__ float g_WT[HID * HID];
__device__ float g_norm_out[N_NODES];
__device__ float g_norm_in[N_NODES];
__device__ int g_din[N_NODES];
__device__ int g_dout[N_NODES];
__device__ int g_row_ptr[N_NODES + 1];
__device__ int g_cursor[N_NODES];
__device__ int g_col[N_EDGES];
__device__ int g_blksum[N_BLK];

__device__ __forceinline__ float tf32_rn(float x) {
    uint32_t r;
    asm("cvt.rna.tf32.f32 %0, %1;" : "=r"(r) : "f"(x));
    return __uint_as_float(r);
}
__device__ __forceinline__ void mma_tf32(float* c, const float* a, const float* b) {
    asm volatile(
        "mma.sync.aligned.m16n8k8.row.col.f32.tf32.tf32.f32 "
        "{%0,%1,%2,%3}, {%4,%5,%6,%7}, {%8,%9}, {%0,%1,%2,%3};"
        : "+f"(c[0]), "+f"(c[1]), "+f"(c[2]), "+f"(c[3])
        : "r"(__float_as_uint(a[0])), "r"(__float_as_uint(a[1])),
          "r"(__float_as_uint(a[2])), "r"(__float_as_uint(a[3])),
          "r"(__float_as_uint(b[0])), "r"(__float_as_uint(b[1])));
}

// ---------------- CSR build ----------------
__global__ void hist_kernel(const int* __restrict__ src, const int* __restrict__ dst) {
    int e = blockIdx.x * blockDim.x + threadIdx.x;
    if (e < N_EDGES) {
        atomicAdd(&g_dout[src[e]], 1);
        atomicAdd(&g_din[dst[e]], 1);
    }
}
__global__ void scan_a() {
    __shared__ int sh[SCAN_B];
    int t = threadIdx.x, idx = blockIdx.x * SCAN_B + t;
    int v = (idx < N_NODES) ? g_din[idx] : 0;
    sh[t] = v;
    __syncthreads();
#pragma unroll
    for (int off = 1; off < SCAN_B; off <<= 1) {
        int add = (t >= off) ? sh[t - off] : 0;
        __syncthreads();
        sh[t] += add;
        __syncthreads();
    }
    if (idx < N_NODES) g_row_ptr[idx + 1] = sh[t];
    if (t == SCAN_B - 1) g_blksum[blockIdx.x] = sh[t];
}
__global__ void scan_c() {
    __shared__ int red[256];
    const int t = threadIdx.x;
    const int chunk = (blockIdx.x * 256) / SCAN_B;
    int part = 0;
    for (int i = t; i < chunk; i += 256) part += g_blksum[i];
    red[t] = part;
    __syncthreads();
#pragma unroll
    for (int o = 128; o > 0; o >>= 1) {
        if (t < o) red[t] += red[t + o];
        __syncthreads();
    }
    const int base = red[0];
    int idx = blockIdx.x * 256 + t;
    if (idx == 0) g_row_ptr[0] = 0;
    if (idx < N_NODES) {
        int inc = g_row_ptr[idx + 1] + base;
        g_row_ptr[idx + 1] = inc;
        g_cursor[idx] = inc - g_din[idx];
        g_norm_in[idx]  = rsqrtf(fmaxf((float)g_din[idx], 1.f));
        g_norm_out[idx] = rsqrtf(fmaxf((float)g_dout[idx], 1.f));
    }
}
__global__ void scatter_kernel(const int* __restrict__ src, const int* __restrict__ dst) {
    int e = blockIdx.x * blockDim.x + threadIdx.x;
    if (e < N_EDGES) {
        int pos = atomicAdd(&g_cursor[dst[e]], 1);
        g_col[pos] = src[e];
    }
}

// ---------------- CSR SpMM (layer 1): gather H[src]*norm_out[src], fused epilogue ----
// out = relu(acc*norm_in + bias) * norm_out   (pre-scale for layer 2 messages)
__global__ void __launch_bounds__(256)
spmm_scaled(const float* __restrict__ X, float* __restrict__ out, const float* __restrict__ bias) {
    int node = blockIdx.x * 4 + (threadIdx.x >> 6);
    if (node >= N_NODES) return;
    int lane = threadIdx.x & 63;
    int beg = g_row_ptr[node], end = g_row_ptr[node + 1];
    float4 acc = make_float4(0.f, 0.f, 0.f, 0.f);
    int e = beg;
    for (; e + 2 <= end; e += 2) {
        int s0 = __ldg(&g_col[e]), s1 = __ldg(&g_col[e + 1]);
        float w0 = __ldg(&g_norm_out[s0]), w1 = __ldg(&g_norm_out[s1]);
        float4 v0 = __ldg(reinterpret_cast<const float4*>(X + (size_t)s0 * HID + lane * 4));
        float4 v1 = __ldg(reinterpret_cast<const float4*>(X + (size_t)s1 * HID + lane * 4));
        acc.x += v0.x * w0 + v1.x * w1;
        acc.y += v0.y * w0 + v1.y * w1;
        acc.z += v0.z * w0 + v1.z * w1;
        acc.w += v0.w * w0 + v1.w * w1;
    }
    if (e < end) {
        int s = __ldg(&g_col[e]);
        float w = __ldg(&g_norm_out[s]);
        float4 v = __ldg(reinterpret_cast<const float4*>(X + (size_t)s * HID + lane * 4));
        acc.x += v.x * w; acc.y += v.y * w; acc.z += v.z * w; acc.w += v.w * w;
    }
    float ni = g_norm_in[node];
    float no = g_norm_out[node];
    float4 b = *reinterpret_cast<const float4*>(bias + lane * 4);
    acc.x = fmaxf(acc.x * ni + b.x, 0.f) * no;
    acc.y = fmaxf(acc.y * ni + b.y, 0.f) * no;
    acc.z = fmaxf(acc.z * ni + b.z, 0.f) * no;
    acc.w = fmaxf(acc.w * ni + b.w, 0.f) * no;
    *reinterpret_cast<float4*>(out + (size_t)node * HID + lane * 4) = acc;
}

// ---------------- tensor-core GEMM (mma.sync tf32), BN = 128, 2 CTA/SM ----------------
// FUSED=false: C = diag(rscale?) * (A[M,K] @ B[256,K]^T) + bias  (opt relu)
// FUSED=true : A row m is gathered on the fly: A[m] = sum_{e in in(m)} AGG[col(e)]
//              (AGG rows already carry norm_out), K=256.
template<bool RELU, bool FUSED>
__global__ void __launch_bounds__(256, 2)
gemm_mma(const float* __restrict__ A, const float* __restrict__ B,
         const float* __restrict__ bias, float* __restrict__ C,
         const float* __restrict__ rscale, int M, int K) {
    __shared__ float As[2][128 * 20];
    __shared__ float Bs[2][128 * 20];

    const int tid = threadIdx.x;
    const int lane = tid & 31;
    const int wid = tid >> 5;
    const int wm = (wid & 1) * 64;
    const int wn = (wid >> 1) * 32;
    const int gid = lane >> 2;
    const int tig = lane & 3;
    const int bm = blockIdx.y * 128;
    const int bn = blockIdx.x * 128;

    // per-thread fixed A rows (2 load slots)
    int rbeg[2] = {0, 0}, rend[2] = {0, 0};
    if (FUSED) {
#pragma unroll
        for (int u = 0; u < 2; u++) {
            int row = (tid + u * 256) >> 2;
            int grow = bm + row;
            if (grow < M) { rbeg[u] = g_row_ptr[grow]; rend[u] = g_row_ptr[grow + 1]; }
        }
    }

    float acc[4][4][4];
#pragma unroll
    for (int i = 0; i < 4; i++)
#pragma unroll
        for (int j = 0; j < 4; j++)
#pragma unroll
            for (int v = 0; v < 4; v++) acc[i][j][v] = 0.f;

    const int nIt = K >> 4;
    float4 pa[2], pb[2];

    // ---- A/B loaders ----
    auto loadA = [&](int u, int k0) -> float4 {
        int idx = tid + u * 256;
        int row = idx >> 2, c4 = idx & 3;
        if (FUSED) {
            float4 s = make_float4(0.f, 0.f, 0.f, 0.f);
            for (int e = rbeg[u]; e < rend[u]; e++) {
                int sc = __ldg(&g_col[e]);
                float4 v = __ldg(reinterpret_cast<const float4*>(A + (size_t)sc * HID + k0 + c4 * 4));
                s.x += v.x; s.y += v.y; s.z += v.z; s.w += v.w;
            }
            return s;
        } else {
            int grow = bm + row;
            if (grow < M)
                return *reinterpret_cast<const float4*>(A + (size_t)grow * K + k0 + c4 * 4);
            return make_float4(0.f, 0.f, 0.f, 0.f);
        }
    };

    // preload + store stage 0
#pragma unroll
    for (int u = 0; u < 2; u++) {
        pa[u] = loadA(u, 0);
        int idx = tid + u * 256;
        int row = idx >> 2, c4 = idx & 3;
        pb[u] = *reinterpret_cast<const float4*>(B + (size_t)(bn + row) * K + c4 * 4);
    }
#pragma unroll
    for (int u = 0; u < 2; u++) {
        int idx = tid + u * 256;
        int row = idx >> 2, c4 = idx & 3;
        float4 va = pa[u], vb = pb[u];
        va.x = tf32_rn(va.x); va.y = tf32_rn(va.y); va.z = tf32_rn(va.z); va.w = tf32_rn(va.w);
        vb.x = tf32_rn(vb.x); vb.y = tf32_rn(vb.y); vb.z = tf32_rn(vb.z); vb.w = tf32_rn(vb.w);
        *reinterpret_cast<float4*>(&As[0][row * 20 + c4 * 4]) = va;
        *reinterpret_cast<float4*>(&Bs[0][row * 20 + c4 * 4]) = vb;
    }
    __syncthreads();

    for (int it = 0; it < nIt; it++) {
        const int s = it & 1;
        const bool more = (it + 1) < nIt;
        if (more) {
            const int k0 = (it + 1) * 16;
#pragma unroll
            for (int u = 0; u < 2; u++) {
                pa[u] = loadA(u, k0);
                int idx = tid + u * 256;
                int row = idx >> 2, c4 = idx & 3;
                pb[u] = *reinterpret_cast<const float4*>(B + (size_t)(bn + row) * K + k0 + c4 * 4);
            }
        }
#pragma unroll
        for (int kk = 0; kk < 2; kk++) {
            const int kb = kk * 8;
            float a[4][4], b[4][2];
#pragma unroll
            for (int i = 0; i < 4; i++) {
                const float* p = &As[s][(wm + i * 16 + gid) * 20 + kb + tig];
                a[i][0] = p[0];
                a[i][1] = p[8 * 20];
                a[i][2] = p[4];
                a[i][3] = p[8 * 20 + 4];
            }
#pragma unroll
            for (int j = 0; j < 4; j++) {
                const float* p = &Bs[s][(wn + j * 8 + gid) * 20 + kb + tig];
                b[j][0] = p[0];
                b[j][1] = p[4];
            }
#pragma unroll
            for (int i = 0; i < 4; i++)
#pragma unroll
                for (int j = 0; j < 4; j++)
                    mma_tf32(acc[i][j], a[i], b[j]);
        }
        if (more) {
            const int ns = s ^ 1;
#pragma unroll
            for (int u = 0; u < 2; u++) {
                int idx = tid + u * 256;
                int row = idx >> 2, c4 = idx & 3;
                float4 va = pa[u], vb = pb[u];
                va.x = tf32_rn(va.x); va.y = tf32_rn(va.y); va.z = tf32_rn(va.z); va.w = tf32_rn(va.w);
                vb.x = tf32_rn(vb.x); vb.y = tf32_rn(vb.y); vb.z = tf32_rn(vb.z); vb.w = tf32_rn(vb.w);
                *reinterpret_cast<float4*>(&As[ns][row * 20 + c4 * 4]) = va;
                *reinterpret_cast<float4*>(&Bs[ns][row * 20 + c4 * 4]) = vb;
            }
        }
        __syncthreads();
    }

#pragma unroll
    for (int j = 0; j < 4; j++) {
        const int col = bn + wn + j * 8 + tig * 2;
        const float bx = bias[col], by = bias[col + 1];
#pragma unroll
        for (int i = 0; i < 4; i++) {
            const int ra = bm + wm + i * 16 + gid;
            const int rb = ra + 8;
            if (ra < M) {
                float s = rscale ? rscale[ra] : 1.f;
                float2 v;
                v.x = acc[i][j][0] * s + bx;
                v.y = acc[i][j][1] * s + by;
                if (RELU) { v.x = fmaxf(v.x, 0.f); v.y = fmaxf(v.y, 0.f); }
                *reinterpret_cast<float2*>(C + (size_t)ra * HID + col) = v;
            }
            if (rb < M) {
                float s = rscale ? rscale[rb] : 1.f;
                float2 v;
                v.x = acc[i][j][2] * s + bx;
                v.y = acc[i][j][3] * s + by;
                if (RELU) { v.x = fmaxf(v.x, 0.f); v.y = fmaxf(v.y, 0.f); }
                *reinterpret_cast<float2*>(C + (size_t)rb * HID + col) = v;
            }
        }
    }
}

// ---------------- transpose gc2_weight [K,N] -> g_WT [N,K] ----------------
__global__ void transpose_kernel(const float* __restrict__ W) {
    __shared__ float t[32][33];
    int bx = blockIdx.x * 32, by = blockIdx.y * 32;
    t[threadIdx.y][threadIdx.x] = W[(size_t)(by + threadIdx.y) * HID + bx + threadIdx.x];
    __syncthreads();
    g_WT[(size_t)(bx + threadIdx.y) * HID + by + threadIdx.x] = t[threadIdx.x][threadIdx.y];
}

__global__ void tail_kernel(const float* __restrict__ sw, float* __restrict__ out, int off) {
    if (threadIdx.x < 5) out[off + threadIdx.x] = sw[threadIdx.x];
}

// ---------------- launch ----------------
extern "C" void kernel_launch(void* const* d_in, const int* in_sizes, int n_in,
                              void* d_out, int out_size) {
    const float* feat0 = (const float*)d_in[0];
    const float* feat1 = (const float*)d_in[1];
    const float* feat2 = (const float*)d_in[2];
    const float* fc_w0 = (const float*)d_in[3];
    const float* fc_b0 = (const float*)d_in[4];
    const float* fc_w1 = (const float*)d_in[5];
    const float* fc_b1 = (const float*)d_in[6];
    const float* fc_w2 = (const float*)d_in[7];
    const float* fc_b2 = (const float*)d_in[8];
    const float* gc1_bias = (const float*)d_in[9];
    const float* gc2_weight = (const float*)d_in[10];
    const float* gc2_bias = (const float*)d_in[11];
    const float* semantic_weight = (const float*)d_in[12];
    const int* src = (const int*)d_in[13];   // JAX x64-disabled -> int32
    const int* dst = (const int*)d_in[14];
    float* out = (float*)d_out;

    float *H = nullptr, *AGG = nullptr, *WT = nullptr, *NI = nullptr;
    void *DIN = nullptr, *DOUT = nullptr;
    cudaGetSymbolAddress((void**)&H, g_H);
    cudaGetSymbolAddress((void**)&AGG, g_AGG);
    cudaGetSymbolAddress((void**)&WT, g_WT);
    cudaGetSymbolAddress((void**)&NI, g_norm_in);
    cudaGetSymbolAddress(&DIN, g_din);
    cudaGetSymbolAddress(&DOUT, g_dout);

    static cudaStream_t sPrep = nullptr;
    static cudaEvent_t evFork = nullptr, evJoin = nullptr;
    if (sPrep == nullptr) {
        cudaStreamCreateWithFlags(&sPrep, cudaStreamNonBlocking);
        cudaEventCreateWithFlags(&evFork, cudaEventDisableTiming);
        cudaEventCreateWithFlags(&evJoin, cudaEventDisableTiming);
    }

    cudaEventRecord(evFork, 0);
    cudaStreamWaitEvent(sPrep, evFork, 0);

    // Launch order arranged so ncu (-s 5 -c 1, counts memsets) profiles gemm0 (fc0).
    cudaMemsetAsync(DIN, 0, N_NODES * sizeof(int), sPrep);                         // 0
    cudaMemsetAsync(DOUT, 0, N_NODES * sizeof(int), sPrep);                        // 1
    gemm_mma<false, false><<<dim3(2, (30000 + 127) / 128), 256>>>(                 // 2
        feat1, fc_w1, fc_b1, H + (size_t)40000 * HID, nullptr, 30000, 256);
    gemm_mma<false, false><<<dim3(2, (30000 + 127) / 128), 256>>>(                 // 3
        feat2, fc_w2, fc_b2, H + (size_t)70000 * HID, nullptr, 30000, 128);
    hist_kernel<<<(N_EDGES + 255) / 256, 256, 0, sPrep>>>(src, dst);               // 4
    gemm_mma<false, false><<<dim3(2, (40000 + 127) / 128), 256>>>(                 // 5 <- profiled
        feat0, fc_w0, fc_b0, H, nullptr, 40000, 512);
    scan_a<<<N_BLK, SCAN_B, 0, sPrep>>>();
    scan_c<<<(N_NODES + 255) / 256, 256, 0, sPrep>>>();
    scatter_kernel<<<(N_EDGES + 255) / 256, 256, 0, sPrep>>>(src, dst);
    transpose_kernel<<<dim3(8, 8), dim3(32, 32), 0, sPrep>>>(gc2_weight);
    cudaEventRecord(evJoin, sPrep);

    cudaStreamWaitEvent(0, evJoin, 0);

    // layer 1: SpMM + fused epilogue (writes AGG, rows pre-scaled by norm_out)
    spmm_scaled<<<(N_NODES + 3) / 4, 256>>>(H, AGG, gc1_bias);
    // layer 2 SpMM fused into the final GEMM's A-gather
    gemm_mma<true, true><<<dim3(2, (N_NODES + 127) / 128), 256>>>(
        AGG, WT, gc2_bias, out, NI, N_NODES, 256);

    tail_kernel<<<1, 32>>>(semantic_weight, out, out_size - 5);
}

// round 10
// speedup vs baseline: 1.4265x; 1.4265x over previous
#include <cuda_runtime.h>
#include <cstdint>

#define N_NODES 100000
#define N_EDGES 300000
#define HID 256
#define SCAN_B 1024
#define N_BLK ((N_NODES + SCAN_B - 1) / SCAN_B)   // 98

// ---------------- scratch ----------------
__device__ float g_H[(size_t)N_NODES * HID];
__device__ float g_AGG[(size_t)N_NODES * HID];
__device__ float g_WT[HID * HID];       // gc2_weight^T, tf32-rounded
__device__ float g_W0[HID * 512];       // fc weights, tf32-rounded
__device__ float g_W1[HID * 256];
__device__ float g_W2[HID * 128];
__device__ float g_norm_out[N_NODES];
__device__ float g_norm_in[N_NODES];
__device__ int g_din[N_NODES];
__device__ int g_dout[N_NODES];
__device__ int g_row_ptr[N_NODES + 1];
__device__ int g_cursor[N_NODES];
__device__ int g_col[N_EDGES];
__device__ int g_blksum[N_BLK];

__device__ __forceinline__ float tf32_rn(float x) {
    uint32_t r;
    asm("cvt.rna.tf32.f32 %0, %1;" : "=r"(r) : "f"(x));
    return __uint_as_float(r);
}
__device__ __forceinline__ void mma_tf32(float* c, const float* a, const float* b) {
    asm volatile(
        "mma.sync.aligned.m16n8k8.row.col.f32.tf32.tf32.f32 "
        "{%0,%1,%2,%3}, {%4,%5,%6,%7}, {%8,%9}, {%0,%1,%2,%3};"
        : "+f"(c[0]), "+f"(c[1]), "+f"(c[2]), "+f"(c[3])
        : "r"(__float_as_uint(a[0])), "r"(__float_as_uint(a[1])),
          "r"(__float_as_uint(a[2])), "r"(__float_as_uint(a[3])),
          "r"(__float_as_uint(b[0])), "r"(__float_as_uint(b[1])));
}

// ---------------- weight pre-conversion (fp32 -> tf32-rounded fp32) ----------------
__global__ void cvt_weights(const float* __restrict__ W, float* __restrict__ out, int n4) {
    int i = blockIdx.x * blockDim.x + threadIdx.x;
    if (i < n4) {
        float4 v = reinterpret_cast<const float4*>(W)[i];
        v.x = tf32_rn(v.x); v.y = tf32_rn(v.y); v.z = tf32_rn(v.z); v.w = tf32_rn(v.w);
        reinterpret_cast<float4*>(out)[i] = v;
    }
}

// ---------------- CSR build ----------------
__global__ void hist_kernel(const int* __restrict__ src, const int* __restrict__ dst) {
    int e = blockIdx.x * blockDim.x + threadIdx.x;
    if (e < N_EDGES) {
        atomicAdd(&g_dout[src[e]], 1);
        atomicAdd(&g_din[dst[e]], 1);
    }
}
__global__ void scan_a() {
    __shared__ int sh[SCAN_B];
    int t = threadIdx.x, idx = blockIdx.x * SCAN_B + t;
    int v = (idx < N_NODES) ? g_din[idx] : 0;
    sh[t] = v;
    __syncthreads();
#pragma unroll
    for (int off = 1; off < SCAN_B; off <<= 1) {
        int add = (t >= off) ? sh[t - off] : 0;
        __syncthreads();
        sh[t] += add;
        __syncthreads();
    }
    if (idx < N_NODES) g_row_ptr[idx + 1] = sh[t];
    if (t == SCAN_B - 1) g_blksum[blockIdx.x] = sh[t];
}
__global__ void scan_c() {
    __shared__ int red[256];
    const int t = threadIdx.x;
    const int chunk = (blockIdx.x * 256) / SCAN_B;
    int part = 0;
    for (int i = t; i < chunk; i += 256) part += g_blksum[i];
    red[t] = part;
    __syncthreads();
#pragma unroll
    for (int o = 128; o > 0; o >>= 1) {
        if (t < o) red[t] += red[t + o];
        __syncthreads();
    }
    const int base = red[0];
    int idx = blockIdx.x * 256 + t;
    if (idx == 0) g_row_ptr[0] = 0;
    if (idx < N_NODES) {
        int inc = g_row_ptr[idx + 1] + base;
        g_row_ptr[idx + 1] = inc;
        g_cursor[idx] = inc - g_din[idx];
        g_norm_in[idx]  = rsqrtf(fmaxf((float)g_din[idx], 1.f));
        g_norm_out[idx] = rsqrtf(fmaxf((float)g_dout[idx], 1.f));
    }
}
__global__ void scatter_kernel(const int* __restrict__ src, const int* __restrict__ dst) {
    int e = blockIdx.x * blockDim.x + threadIdx.x;
    if (e < N_EDGES) {
        int pos = atomicAdd(&g_cursor[dst[e]], 1);
        g_col[pos] = src[e];
    }
}

// ---------------- CSR SpMM (layer 1): gather H[src]*norm_out[src], fused epilogue ----
__global__ void __launch_bounds__(256)
spmm_scaled(const float* __restrict__ X, float* __restrict__ out, const float* __restrict__ bias) {
    int node = blockIdx.x * 4 + (threadIdx.x >> 6);
    if (node >= N_NODES) return;
    int lane = threadIdx.x & 63;
    int beg = g_row_ptr[node], end = g_row_ptr[node + 1];
    float4 acc = make_float4(0.f, 0.f, 0.f, 0.f);
    int e = beg;
    for (; e + 2 <= end; e += 2) {
        int s0 = __ldg(&g_col[e]), s1 = __ldg(&g_col[e + 1]);
        float w0 = __ldg(&g_norm_out[s0]), w1 = __ldg(&g_norm_out[s1]);
        float4 v0 = __ldg(reinterpret_cast<const float4*>(X + (size_t)s0 * HID + lane * 4));
        float4 v1 = __ldg(reinterpret_cast<const float4*>(X + (size_t)s1 * HID + lane * 4));
        acc.x += v0.x * w0 + v1.x * w1;
        acc.y += v0.y * w0 + v1.y * w1;
        acc.z += v0.z * w0 + v1.z * w1;
        acc.w += v0.w * w0 + v1.w * w1;
    }
    if (e < end) {
        int s = __ldg(&g_col[e]);
        float w = __ldg(&g_norm_out[s]);
        float4 v = __ldg(reinterpret_cast<const float4*>(X + (size_t)s * HID + lane * 4));
        acc.x += v.x * w; acc.y += v.y * w; acc.z += v.z * w; acc.w += v.w * w;
    }
    float ni = g_norm_in[node];
    float no = g_norm_out[node];
    float4 b = *reinterpret_cast<const float4*>(bias + lane * 4);
    acc.x = fmaxf(acc.x * ni + b.x, 0.f) * no;
    acc.y = fmaxf(acc.y * ni + b.y, 0.f) * no;
    acc.z = fmaxf(acc.z * ni + b.z, 0.f) * no;
    acc.w = fmaxf(acc.w * ni + b.w, 0.f) * no;
    *reinterpret_cast<float4*>(out + (size_t)node * HID + lane * 4) = acc;
}

// ---------------- CSR SpMM (layer 2): plain gather-sum ----------------
__global__ void __launch_bounds__(256)
spmm_plain(const float* __restrict__ X, float* __restrict__ out) {
    int node = blockIdx.x * 4 + (threadIdx.x >> 6);
    if (node >= N_NODES) return;
    int lane = threadIdx.x & 63;
    int beg = g_row_ptr[node], end = g_row_ptr[node + 1];
    float4 acc = make_float4(0.f, 0.f, 0.f, 0.f);
    int e = beg;
    for (; e + 2 <= end; e += 2) {
        int s0 = __ldg(&g_col[e]), s1 = __ldg(&g_col[e + 1]);
        float4 v0 = __ldg(reinterpret_cast<const float4*>(X + (size_t)s0 * HID + lane * 4));
        float4 v1 = __ldg(reinterpret_cast<const float4*>(X + (size_t)s1 * HID + lane * 4));
        acc.x += v0.x + v1.x; acc.y += v0.y + v1.y;
        acc.z += v0.z + v1.z; acc.w += v0.w + v1.w;
    }
    if (e < end) {
        int s = __ldg(&g_col[e]);
        float4 v = __ldg(reinterpret_cast<const float4*>(X + (size_t)s * HID + lane * 4));
        acc.x += v.x; acc.y += v.y; acc.z += v.z; acc.w += v.w;
    }
    *reinterpret_cast<float4*>(out + (size_t)node * HID + lane * 4) = acc;
}

// ---------------- tensor-core GEMM (mma.sync tf32), BN=128, 2 CTA/SM ----------------
// C[M,256] = diag(rscale?) * (A[M,K] @ B[256,K]^T) + bias  (opt relu)
// B is PRE-ROUNDED to tf32 (no cvt on the B path).
template<bool RELU>
__global__ void __launch_bounds__(256, 2)
gemm_mma(const float* __restrict__ A, const float* __restrict__ B,
         const float* __restrict__ bias, float* __restrict__ C,
         const float* __restrict__ rscale, int M, int K) {
    __shared__ float As[2][128 * 20];
    __shared__ float Bs[2][128 * 20];

    const int tid = threadIdx.x;
    const int lane = tid & 31;
    const int wid = tid >> 5;
    const int wm = (wid & 1) * 64;
    const int wn = (wid >> 1) * 32;
    const int gid = lane >> 2;
    const int tig = lane & 3;
    const int bm = blockIdx.y * 128;
    const int bn = blockIdx.x * 128;

    float acc[4][4][4];
#pragma unroll
    for (int i = 0; i < 4; i++)
#pragma unroll
        for (int j = 0; j < 4; j++)
#pragma unroll
            for (int v = 0; v < 4; v++) acc[i][j][v] = 0.f;

    const int nIt = K >> 4;
    float4 pa[2], pb[2];
#pragma unroll
    for (int u = 0; u < 2; u++) {
        int idx = tid + u * 256;
        int row = idx >> 2, c4 = idx & 3;
        pa[u] = make_float4(0.f, 0.f, 0.f, 0.f);
        if (bm + row < M)
            pa[u] = *reinterpret_cast<const float4*>(A + (size_t)(bm + row) * K + c4 * 4);
        pb[u] = *reinterpret_cast<const float4*>(B + (size_t)(bn + row) * K + c4 * 4);
    }
#pragma unroll
    for (int u = 0; u < 2; u++) {
        int idx = tid + u * 256;
        int row = idx >> 2, c4 = idx & 3;
        float4 va = pa[u];
        va.x = tf32_rn(va.x); va.y = tf32_rn(va.y); va.z = tf32_rn(va.z); va.w = tf32_rn(va.w);
        *reinterpret_cast<float4*>(&As[0][row * 20 + c4 * 4]) = va;
        *reinterpret_cast<float4*>(&Bs[0][row * 20 + c4 * 4]) = pb[u];  // pre-rounded
    }
    __syncthreads();

    for (int it = 0; it < nIt; it++) {
        const int s = it & 1;
        const bool more = (it + 1) < nIt;
        if (more) {
            const int k0 = (it + 1) * 16;
#pragma unroll
            for (int u = 0; u < 2; u++) {
                int idx = tid + u * 256;
                int row = idx >> 2, c4 = idx & 3;
                pa[u] = make_float4(0.f, 0.f, 0.f, 0.f);
                if (bm + row < M)
                    pa[u] = *reinterpret_cast<const float4*>(A + (size_t)(bm + row) * K + k0 + c4 * 4);
                pb[u] = *reinterpret_cast<const float4*>(B + (size_t)(bn + row) * K + k0 + c4 * 4);
            }
        }
#pragma unroll
        for (int kk = 0; kk < 2; kk++) {
            const int kb = kk * 8;
            float a[4][4], b[4][2];
#pragma unroll
            for (int i = 0; i < 4; i++) {
                const float* p = &As[s][(wm + i * 16 + gid) * 20 + kb + tig];
                a[i][0] = p[0];
                a[i][1] = p[8 * 20];
                a[i][2] = p[4];
                a[i][3] = p[8 * 20 + 4];
            }
#pragma unroll
            for (int j = 0; j < 4; j++) {
                const float* p = &Bs[s][(wn + j * 8 + gid) * 20 + kb + tig];
                b[j][0] = p[0];
                b[j][1] = p[4];
            }
#pragma unroll
            for (int i = 0; i < 4; i++)
#pragma unroll
                for (int j = 0; j < 4; j++)
                    mma_tf32(acc[i][j], a[i], b[j]);
        }
        if (more) {
            const int ns = s ^ 1;
#pragma unroll
            for (int u = 0; u < 2; u++) {
                int idx = tid + u * 256;
                int row = idx >> 2, c4 = idx & 3;
                float4 va = pa[u];
                va.x = tf32_rn(va.x); va.y = tf32_rn(va.y); va.z = tf32_rn(va.z); va.w = tf32_rn(va.w);
                *reinterpret_cast<float4*>(&As[ns][row * 20 + c4 * 4]) = va;
                *reinterpret_cast<float4*>(&Bs[ns][row * 20 + c4 * 4]) = pb[u];
            }
        }
        __syncthreads();
    }

#pragma unroll
    for (int j = 0; j < 4; j++) {
        const int col = bn + wn + j * 8 + tig * 2;
        const float bx = bias[col], by = bias[col + 1];
#pragma unroll
        for (int i = 0; i < 4; i++) {
            const int ra = bm + wm + i * 16 + gid;
            const int rb = ra + 8;
            if (ra < M) {
                float s = rscale ? rscale[ra] : 1.f;
                float2 v;
                v.x = acc[i][j][0] * s + bx;
                v.y = acc[i][j][1] * s + by;
                if (RELU) { v.x = fmaxf(v.x, 0.f); v.y = fmaxf(v.y, 0.f); }
                *reinterpret_cast<float2*>(C + (size_t)ra * HID + col) = v;
            }
            if (rb < M) {
                float s = rscale ? rscale[rb] : 1.f;
                float2 v;
                v.x = acc[i][j][2] * s + bx;
                v.y = acc[i][j][3] * s + by;
                if (RELU) { v.x = fmaxf(v.x, 0.f); v.y = fmaxf(v.y, 0.f); }
                *reinterpret_cast<float2*>(C + (size_t)rb * HID + col) = v;
            }
        }
    }
}

// ---------------- transpose gc2_weight [K,N] -> g_WT [N,K], tf32-rounded ----------------
__global__ void transpose_kernel(const float* __restrict__ W) {
    __shared__ float t[32][33];
    int bx = blockIdx.x * 32, by = blockIdx.y * 32;
    t[threadIdx.y][threadIdx.x] = W[(size_t)(by + threadIdx.y) * HID + bx + threadIdx.x];
    __syncthreads();
    g_WT[(size_t)(bx + threadIdx.y) * HID + by + threadIdx.x] = tf32_rn(t[threadIdx.x][threadIdx.y]);
}

__global__ void tail_kernel(const float* __restrict__ sw, float* __restrict__ out, int off) {
    if (threadIdx.x < 5) out[off + threadIdx.x] = sw[threadIdx.x];
}

// ---------------- launch ----------------
extern "C" void kernel_launch(void* const* d_in, const int* in_sizes, int n_in,
                              void* d_out, int out_size) {
    const float* feat0 = (const float*)d_in[0];
    const float* feat1 = (const float*)d_in[1];
    const float* feat2 = (const float*)d_in[2];
    const float* fc_w0 = (const float*)d_in[3];
    const float* fc_b0 = (const float*)d_in[4];
    const float* fc_w1 = (const float*)d_in[5];
    const float* fc_b1 = (const float*)d_in[6];
    const float* fc_w2 = (const float*)d_in[7];
    const float* fc_b2 = (const float*)d_in[8];
    const float* gc1_bias = (const float*)d_in[9];
    const float* gc2_weight = (const float*)d_in[10];
    const float* gc2_bias = (const float*)d_in[11];
    const float* semantic_weight = (const float*)d_in[12];
    const int* src = (const int*)d_in[13];   // JAX x64-disabled -> int32
    const int* dst = (const int*)d_in[14];
    float* out = (float*)d_out;

    float *H = nullptr, *AGG = nullptr, *WT = nullptr, *NI = nullptr;
    float *W0 = nullptr, *W1 = nullptr, *W2 = nullptr;
    void *DIN = nullptr, *DOUT = nullptr;
    cudaGetSymbolAddress((void**)&H, g_H);
    cudaGetSymbolAddress((void**)&AGG, g_AGG);
    cudaGetSymbolAddress((void**)&WT, g_WT);
    cudaGetSymbolAddress((void**)&NI, g_norm_in);
    cudaGetSymbolAddress((void**)&W0, g_W0);
    cudaGetSymbolAddress((void**)&W1, g_W1);
    cudaGetSymbolAddress((void**)&W2, g_W2);
    cudaGetSymbolAddress(&DIN, g_din);
    cudaGetSymbolAddress(&DOUT, g_dout);

    static cudaStream_t sPrep = nullptr;
    static cudaEvent_t evFork = nullptr, evJoin = nullptr;
    if (sPrep == nullptr) {
        cudaStreamCreateWithFlags(&sPrep, cudaStreamNonBlocking);
        cudaEventCreateWithFlags(&evFork, cudaEventDisableTiming);
        cudaEventCreateWithFlags(&evJoin, cudaEventDisableTiming);
    }

    // fork point at the very start: prep branch depends on nothing on main
    cudaEventRecord(evFork, 0);
    cudaStreamWaitEvent(sPrep, evFork, 0);

    // ---- main stream: weight conversions then fc GEMMs (launch idx 5 = fc0, profiled) ----
    cvt_weights<<<(HID * 512 / 4 + 255) / 256, 256>>>(fc_w0, W0, HID * 512 / 4);   // 0
    cvt_weights<<<(HID * 256 / 4 + 255) / 256, 256>>>(fc_w1, W1, HID * 256 / 4);   // 1
    cvt_weights<<<(HID * 128 / 4 + 255) / 256, 256>>>(fc_w2, W2, HID * 128 / 4);   // 2
    gemm_mma<false><<<dim3(2, (30000 + 127) / 128), 256>>>(                        // 3
        feat1, W1, fc_b1, H + (size_t)40000 * HID, nullptr, 30000, 256);
    gemm_mma<false><<<dim3(2, (30000 + 127) / 128), 256>>>(                        // 4
        feat2, W2, fc_b2, H + (size_t)70000 * HID, nullptr, 30000, 128);
    gemm_mma<false><<<dim3(2, (40000 + 127) / 128), 256>>>(                        // 5 <- profiled
        feat0, W0, fc_b0, H, nullptr, 40000, 512);

    // ---- prep stream: CSR build + norms + weight transpose ----
    cudaMemsetAsync(DIN, 0, N_NODES * sizeof(int), sPrep);
    cudaMemsetAsync(DOUT, 0, N_NODES * sizeof(int), sPrep);
    hist_kernel<<<(N_EDGES + 255) / 256, 256, 0, sPrep>>>(src, dst);
    scan_a<<<N_BLK, SCAN_B, 0, sPrep>>>();
    scan_c<<<(N_NODES + 255) / 256, 256, 0, sPrep>>>();
    scatter_kernel<<<(N_EDGES + 255) / 256, 256, 0, sPrep>>>(src, dst);
    transpose_kernel<<<dim3(8, 8), dim3(32, 32), 0, sPrep>>>(gc2_weight);
    cudaEventRecord(evJoin, sPrep);

    // ---- join, then graph layers ----
    cudaStreamWaitEvent(0, evJoin, 0);

    spmm_scaled<<<(N_NODES + 3) / 4, 256>>>(H, AGG, gc1_bias);
    spmm_plain<<<(N_NODES + 3) / 4, 256>>>(AGG, H);
    gemm_mma<true><<<dim3(2, (N_NODES + 127) / 128), 256>>>(
        H, WT, gc2_bias, out, NI, N_NODES, 256);

    tail_kernel<<<1, 32>>>(semantic_weight, out, out_size - 5);
}